// round 1
// baseline (speedup 1.0000x reference)
#include <cuda_runtime.h>
#include <math.h>

#define BATCH   4
#define LSEQ    8192
#define DMODEL  1024
#define NHEADS  16
#define DHEAD   64
#define MROWS   (BATCH * LSEQ)          // 32768
#define NCHUNK  8                       // split-K chunks over L for Kv reduction
#define EPSV    1e-6f

// ---------------- scratch (device globals; no allocations allowed) ----------
static __device__ float g_Qf  [(size_t)MROWS * DMODEL];                 // phi(x@Wq)
static __device__ float g_Kf  [(size_t)MROWS * DMODEL];                 // phi(x@Wk)
static __device__ float g_V   [(size_t)MROWS * DMODEL];                 // x@Wv
static __device__ float g_attn[(size_t)MROWS * DMODEL];                 // attention out (pre-Wo)
static __device__ float g_KvP [(size_t)NCHUNK * BATCH * NHEADS * DHEAD * DHEAD];
static __device__ float g_K1P [(size_t)NCHUNK * BATCH * NHEADS * DHEAD];
static __device__ float g_Kv  [(size_t)BATCH * NHEADS * DHEAD * DHEAD];
static __device__ float g_K1  [(size_t)BATCH * NHEADS * DHEAD];

// ---------------- SGEMM: C[M,N] = A[M,K] @ B[K,N], optional phi epilogue ----
// 128x128 block tile, BK=8, 256 threads, 8x8 micro-tile per thread.
template <int PHI>
__global__ __launch_bounds__(256, 2)
void sgemm_kernel(const float* __restrict__ A, const float* __restrict__ B,
                  float* __restrict__ C, int M, int N, int K)
{
    __shared__ float As[8][128];
    __shared__ float Bs[8][132];   // padded row (132%4==0 keeps float4 alignment)

    const int tid  = threadIdx.x;
    const int bm   = blockIdx.y * 128;
    const int bn   = blockIdx.x * 128;

    const int arow = tid >> 1;            // 0..127
    const int acol = (tid & 1) * 4;       // 0 or 4
    const int brow = tid >> 5;            // 0..7
    const int bcol = (tid & 31) * 4;      // 0..124

    const int tx = tid & 15;              // col group
    const int ty = tid >> 4;              // row group

    float acc[8][8];
    #pragma unroll
    for (int i = 0; i < 8; i++)
        #pragma unroll
        for (int j = 0; j < 8; j++) acc[i][j] = 0.f;

    const float* Arow = A + (size_t)(bm + arow) * K;

    for (int kt = 0; kt < K; kt += 8) {
        float4 av = *(const float4*)(Arow + kt + acol);
        As[acol + 0][arow] = av.x;
        As[acol + 1][arow] = av.y;
        As[acol + 2][arow] = av.z;
        As[acol + 3][arow] = av.w;
        float4 bv = *(const float4*)(B + (size_t)(kt + brow) * N + bn + bcol);
        *(float4*)&Bs[brow][bcol] = bv;
        __syncthreads();

        #pragma unroll
        for (int k = 0; k < 8; k++) {
            float ar[8], br[8];
            float4 a0 = *(const float4*)&As[k][ty * 8];
            float4 a1 = *(const float4*)&As[k][ty * 8 + 4];
            ar[0]=a0.x; ar[1]=a0.y; ar[2]=a0.z; ar[3]=a0.w;
            ar[4]=a1.x; ar[5]=a1.y; ar[6]=a1.z; ar[7]=a1.w;
            float4 b0 = *(const float4*)&Bs[k][tx * 8];
            float4 b1 = *(const float4*)&Bs[k][tx * 8 + 4];
            br[0]=b0.x; br[1]=b0.y; br[2]=b0.z; br[3]=b0.w;
            br[4]=b1.x; br[5]=b1.y; br[6]=b1.z; br[7]=b1.w;
            #pragma unroll
            for (int i = 0; i < 8; i++)
                #pragma unroll
                for (int j = 0; j < 8; j++)
                    acc[i][j] = fmaf(ar[i], br[j], acc[i][j]);
        }
        __syncthreads();
    }

    #pragma unroll
    for (int i = 0; i < 8; i++) {
        float* crow = C + (size_t)(bm + ty * 8 + i) * N + bn + tx * 8;
        float v[8];
        #pragma unroll
        for (int j = 0; j < 8; j++) {
            float t = acc[i][j];
            if (PHI) t = (t > 0.f) ? (t + 1.f) : __expf(t);   // elu(x)+1
            v[j] = t;
        }
        *(float4*)(crow)     = make_float4(v[0], v[1], v[2], v[3]);
        *(float4*)(crow + 4) = make_float4(v[4], v[5], v[6], v[7]);
    }
}

// ---------------- Kv / K1 split-K partial reduction -------------------------
// grid (NCHUNK, H, B), 256 threads. Each block: partial over L/NCHUNK = 1024
// positions, processed in 16 sub-tiles of 64 rows staged in shared memory.
__global__ __launch_bounds__(256, 4)
void kv_reduce_kernel()
{
    const int chunk = blockIdx.x;
    const int h     = blockIdx.y;
    const int b     = blockIdx.z;
    const int bh    = b * NHEADS + h;
    const int tid   = threadIdx.x;

    __shared__ float sK[64][65];
    __shared__ float sV[64][65];

    const int tm = (tid >> 4) * 4;   // 0..60
    const int tn = (tid & 15) * 4;   // 0..60

    float acc[4][4];
    #pragma unroll
    for (int i = 0; i < 4; i++)
        #pragma unroll
        for (int j = 0; j < 4; j++) acc[i][j] = 0.f;
    float k1acc = 0.f;

    for (int sub = 0; sub < 16; sub++) {
        const int l0 = chunk * (LSEQ / NCHUNK) + sub * 64;
        // load 64x64 tiles of Kf and V for this head
        for (int i = tid; i < 64 * 16; i += 256) {     // float4 units
            int r  = i >> 4;
            int c4 = (i & 15) << 2;
            size_t base = ((size_t)b * LSEQ + l0 + r) * DMODEL + h * DHEAD + c4;
            float4 kv = *(const float4*)(g_Kf + base);
            sK[r][c4+0]=kv.x; sK[r][c4+1]=kv.y; sK[r][c4+2]=kv.z; sK[r][c4+3]=kv.w;
            float4 vv = *(const float4*)(g_V + base);
            sV[r][c4+0]=vv.x; sV[r][c4+1]=vv.y; sV[r][c4+2]=vv.z; sV[r][c4+3]=vv.w;
        }
        __syncthreads();

        #pragma unroll 4
        for (int l = 0; l < 64; l++) {
            float a0 = sK[l][tm+0], a1 = sK[l][tm+1], a2 = sK[l][tm+2], a3 = sK[l][tm+3];
            float b0 = sV[l][tn+0], b1 = sV[l][tn+1], b2 = sV[l][tn+2], b3 = sV[l][tn+3];
            acc[0][0]+=a0*b0; acc[0][1]+=a0*b1; acc[0][2]+=a0*b2; acc[0][3]+=a0*b3;
            acc[1][0]+=a1*b0; acc[1][1]+=a1*b1; acc[1][2]+=a1*b2; acc[1][3]+=a1*b3;
            acc[2][0]+=a2*b0; acc[2][1]+=a2*b1; acc[2][2]+=a2*b2; acc[2][3]+=a2*b3;
            acc[3][0]+=a3*b0; acc[3][1]+=a3*b1; acc[3][2]+=a3*b2; acc[3][3]+=a3*b3;
        }
        if (tid < 64) {
            #pragma unroll 4
            for (int l = 0; l < 64; l++) k1acc += sK[l][tid];
        }
        __syncthreads();
    }

    // write partials (deterministic, no atomics)
    #pragma unroll
    for (int i = 0; i < 4; i++)
        #pragma unroll
        for (int j = 0; j < 4; j++)
            g_KvP[(((size_t)chunk * (BATCH*NHEADS) + bh) * DHEAD + tm + i) * DHEAD + tn + j] = acc[i][j];
    if (tid < 64)
        g_K1P[((size_t)chunk * (BATCH*NHEADS) + bh) * DHEAD + tid] = k1acc;
}

// ---------------- reduce partials across chunks ------------------------------
__global__ void kv_finalize_kernel()
{
    const int i = blockIdx.x * blockDim.x + threadIdx.x;
    const int KV_ELEMS = BATCH * NHEADS * DHEAD * DHEAD;   // 262144
    const int K1_ELEMS = BATCH * NHEADS * DHEAD;           // 4096
    if (i < KV_ELEMS) {
        float s = 0.f;
        #pragma unroll
        for (int c = 0; c < NCHUNK; c++) s += g_KvP[(size_t)c * KV_ELEMS + i];
        g_Kv[i] = s;
    }
    if (i < K1_ELEMS) {
        float s = 0.f;
        #pragma unroll
        for (int c = 0; c < NCHUNK; c++) s += g_K1P[(size_t)c * K1_ELEMS + i];
        g_K1[i] = s;
    }
}

// ---------------- apply: attn = (Qf @ Kv) / (Qf @ K1 + eps) ------------------
// grid (L/64, H, B), 256 threads. One 64-row x 64-col (one head) tile.
__global__ __launch_bounds__(256, 4)
void attn_apply_kernel()
{
    const int lt = blockIdx.x;
    const int h  = blockIdx.y;
    const int b  = blockIdx.z;
    const int bh = b * NHEADS + h;
    const int tid = threadIdx.x;

    __shared__ float sQ [64][65];
    __shared__ float sKv[64][65];
    __shared__ float sK1[64];
    __shared__ float sden[64];

    // load Q tile (64 rows x 64 cols of this head) and Kv (64x64)
    for (int i = tid; i < 64 * 16; i += 256) {
        int r  = i >> 4;
        int c4 = (i & 15) << 2;
        size_t qbase = ((size_t)b * LSEQ + lt * 64 + r) * DMODEL + h * DHEAD + c4;
        float4 qv = *(const float4*)(g_Qf + qbase);
        sQ[r][c4+0]=qv.x; sQ[r][c4+1]=qv.y; sQ[r][c4+2]=qv.z; sQ[r][c4+3]=qv.w;
        float4 kv = *(const float4*)(g_Kv + ((size_t)bh * DHEAD + r) * DHEAD + c4);
        sKv[r][c4+0]=kv.x; sKv[r][c4+1]=kv.y; sKv[r][c4+2]=kv.z; sKv[r][c4+3]=kv.w;
    }
    if (tid < 64) sK1[tid] = g_K1[(size_t)bh * DHEAD + tid];
    __syncthreads();

    if (tid < 64) {
        float d = 0.f;
        #pragma unroll
        for (int m = 0; m < 64; m++) d += sQ[tid][m] * sK1[m];
        sden[tid] = d + EPSV;
    }
    __syncthreads();

    const int tm = (tid >> 4) * 4;
    const int tn = (tid & 15) * 4;
    float acc[4][4];
    #pragma unroll
    for (int i = 0; i < 4; i++)
        #pragma unroll
        for (int j = 0; j < 4; j++) acc[i][j] = 0.f;

    #pragma unroll 4
    for (int m = 0; m < 64; m++) {
        float a0 = sQ[tm+0][m], a1 = sQ[tm+1][m], a2 = sQ[tm+2][m], a3 = sQ[tm+3][m];
        float b0 = sKv[m][tn+0], b1 = sKv[m][tn+1], b2 = sKv[m][tn+2], b3 = sKv[m][tn+3];
        acc[0][0]+=a0*b0; acc[0][1]+=a0*b1; acc[0][2]+=a0*b2; acc[0][3]+=a0*b3;
        acc[1][0]+=a1*b0; acc[1][1]+=a1*b1; acc[1][2]+=a1*b2; acc[1][3]+=a1*b3;
        acc[2][0]+=a2*b0; acc[2][1]+=a2*b1; acc[2][2]+=a2*b2; acc[2][3]+=a2*b3;
        acc[3][0]+=a3*b0; acc[3][1]+=a3*b1; acc[3][2]+=a3*b2; acc[3][3]+=a3*b3;
    }

    #pragma unroll
    for (int i = 0; i < 4; i++) {
        float inv = 1.f / sden[tm + i];
        size_t base = ((size_t)b * LSEQ + lt * 64 + tm + i) * DMODEL + h * DHEAD + tn;
        *(float4*)(g_attn + base) =
            make_float4(acc[i][0]*inv, acc[i][1]*inv, acc[i][2]*inv, acc[i][3]*inv);
    }
}

// ---------------- launch ------------------------------------------------------
extern "C" void kernel_launch(void* const* d_in, const int* in_sizes, int n_in,
                              void* d_out, int out_size)
{
    const float* x  = (const float*)d_in[0];
    const float* Wq = (const float*)d_in[1];
    const float* Wk = (const float*)d_in[2];
    const float* Wv = (const float*)d_in[3];
    const float* Wo = (const float*)d_in[4];
    float* out = (float*)d_out;

    float *pQf, *pKf, *pV, *pAttn;
    cudaGetSymbolAddress((void**)&pQf,   g_Qf);
    cudaGetSymbolAddress((void**)&pKf,   g_Kf);
    cudaGetSymbolAddress((void**)&pV,    g_V);
    cudaGetSymbolAddress((void**)&pAttn, g_attn);

    dim3 gemm_grid(DMODEL / 128, MROWS / 128);   // (8, 256)

    // projections (+ fused phi on Q, K)
    sgemm_kernel<1><<<gemm_grid, 256>>>(x, Wq, pQf, MROWS, DMODEL, DMODEL);
    sgemm_kernel<1><<<gemm_grid, 256>>>(x, Wk, pKf, MROWS, DMODEL, DMODEL);
    sgemm_kernel<0><<<gemm_grid, 256>>>(x, Wv, pV,  MROWS, DMODEL, DMODEL);

    // global Kv / K1 reduction (split-K, deterministic)
    kv_reduce_kernel<<<dim3(NCHUNK, NHEADS, BATCH), 256>>>();
    kv_finalize_kernel<<<(BATCH*NHEADS*DHEAD*DHEAD + 255) / 256, 256>>>();

    // attention apply
    attn_apply_kernel<<<dim3(LSEQ / 64, NHEADS, BATCH), 256>>>();

    // output projection
    sgemm_kernel<0><<<gemm_grid, 256>>>(pAttn, Wo, out, MROWS, DMODEL, DMODEL);
}

// round 4
// speedup vs baseline: 2.7055x; 2.7055x over previous
#include <cuda_runtime.h>
#include <math.h>

#define BATCH   4
#define LSEQ    8192
#define DMODEL  1024
#define NHEADS  16
#define DHEAD   64
#define MROWS   (BATCH * LSEQ)          // 32768
#define NCHUNK  8
#define EPSV    1e-6f

// ---------------- scratch (device globals; no allocations allowed) ----------
static __device__ float g_Qf  [(size_t)MROWS * DMODEL];
static __device__ float g_Kf  [(size_t)MROWS * DMODEL];
static __device__ float g_V   [(size_t)MROWS * DMODEL];
static __device__ float g_attn[(size_t)MROWS * DMODEL];
static __device__ float g_KvP [(size_t)NCHUNK * BATCH * NHEADS * DHEAD * DHEAD];
static __device__ float g_K1P [(size_t)NCHUNK * BATCH * NHEADS * DHEAD];
static __device__ float g_Kv  [(size_t)BATCH * NHEADS * DHEAD * DHEAD];
static __device__ float g_K1  [(size_t)BATCH * NHEADS * DHEAD];

// ---------------- TF32 helpers ----------------------------------------------
__device__ __forceinline__ float f2tf32(float x) {
    unsigned r;
    asm("cvt.rna.tf32.f32 %0, %1;" : "=r"(r) : "f"(x));
    return __uint_as_float(r);
}

__device__ __forceinline__ void mma_tf32(float c[4],
                                         unsigned a0, unsigned a1, unsigned a2, unsigned a3,
                                         unsigned b0, unsigned b1)
{
    asm volatile("mma.sync.aligned.m16n8k8.row.col.f32.tf32.tf32.f32 "
                 "{%0,%1,%2,%3}, {%4,%5,%6,%7}, {%8,%9}, {%0,%1,%2,%3};"
                 : "+f"(c[0]), "+f"(c[1]), "+f"(c[2]), "+f"(c[3])
                 : "r"(a0), "r"(a1), "r"(a2), "r"(a3), "r"(b0), "r"(b1));
}

// ---------------- TF32 tensor-core GEMM --------------------------------------
// C[M,N] = A[M,K] @ B[K,N].  128x128 block tile, BK=16, 256 threads (8 warps,
// 2x4), each warp 64x32 via 4x4 m16n8k8 MMAs. Double-buffered smem.
// As pad 20 / Bs pad 136 make all fragment LDS bank-conflict-free.
template <int PHI>
__global__ __launch_bounds__(256, 2)
void gemm_tf32_kernel(const float* __restrict__ A, const float* __restrict__ B,
                      float* __restrict__ C, int M, int N, int K)
{
    __shared__ __align__(16) float As[2][128][20];
    __shared__ __align__(16) float Bs[2][16][136];

    const int tid  = threadIdx.x;
    const int bm   = blockIdx.y * 128;
    const int bn   = blockIdx.x * 128;
    const int lane = tid & 31;
    const int warp = tid >> 5;
    const int wm   = (warp >> 2) * 64;   // 0 or 64
    const int wn   = (warp & 3) * 32;    // 0,32,64,96
    const int lr   = lane >> 2;          // 0..7
    const int lc   = lane & 3;           // 0..3

    // staging indices: A tile 128x16 = 512 float4 (2/thread), B tile 16x128 same
    const int ar0 = tid >> 2;            // idx=tid   -> rows 0..63
    const int ac0 = (tid & 3) * 4;
    const int ar1 = (tid + 256) >> 2;    // rows 64..127
    const int br0 = tid >> 5;            // rows 0..7
    const int bc0 = (tid & 31) * 4;
    const int br1 = (tid + 256) >> 5;    // rows 8..15

    float acc[4][4][4];
    #pragma unroll
    for (int mt = 0; mt < 4; mt++)
        #pragma unroll
        for (int nt = 0; nt < 4; nt++)
            #pragma unroll
            for (int i = 0; i < 4; i++) acc[mt][nt][i] = 0.f;

    const int KT = K >> 4;               // 64 tiles

    float4 la0, la1, lb0, lb1;
    // prologue load (kt = 0)
    la0 = *(const float4*)(A + (size_t)(bm + ar0) * K + ac0);
    la1 = *(const float4*)(A + (size_t)(bm + ar1) * K + ac0);
    lb0 = *(const float4*)(B + (size_t)(br0) * N + bn + bc0);
    lb1 = *(const float4*)(B + (size_t)(br1) * N + bn + bc0);

    #pragma unroll 1
    for (int kt = 0; kt < KT; kt++) {
        const int buf = kt & 1;
        // store staged regs (converted to tf32) into current buffer
        *(float4*)&As[buf][ar0][ac0] =
            make_float4(f2tf32(la0.x), f2tf32(la0.y), f2tf32(la0.z), f2tf32(la0.w));
        *(float4*)&As[buf][ar1][ac0] =
            make_float4(f2tf32(la1.x), f2tf32(la1.y), f2tf32(la1.z), f2tf32(la1.w));
        *(float4*)&Bs[buf][br0][bc0] =
            make_float4(f2tf32(lb0.x), f2tf32(lb0.y), f2tf32(lb0.z), f2tf32(lb0.w));
        *(float4*)&Bs[buf][br1][bc0] =
            make_float4(f2tf32(lb1.x), f2tf32(lb1.y), f2tf32(lb1.z), f2tf32(lb1.w));
        __syncthreads();

        // issue next tile's global loads (overlap with compute)
        if (kt + 1 < KT) {
            const int ko = (kt + 1) << 4;
            la0 = *(const float4*)(A + (size_t)(bm + ar0) * K + ko + ac0);
            la1 = *(const float4*)(A + (size_t)(bm + ar1) * K + ko + ac0);
            lb0 = *(const float4*)(B + (size_t)(ko + br0) * N + bn + bc0);
            lb1 = *(const float4*)(B + (size_t)(ko + br1) * N + bn + bc0);
        }

        // compute on current buffer
        #pragma unroll
        for (int ks = 0; ks < 2; ks++) {
            const int k0 = ks * 8;
            unsigned bfr[4][2];
            #pragma unroll
            for (int nt = 0; nt < 4; nt++) {
                bfr[nt][0] = __float_as_uint(Bs[buf][k0 + lc    ][wn + nt * 8 + lr]);
                bfr[nt][1] = __float_as_uint(Bs[buf][k0 + lc + 4][wn + nt * 8 + lr]);
            }
            #pragma unroll
            for (int mt = 0; mt < 4; mt++) {
                const int mr = wm + mt * 16 + lr;
                unsigned a0 = __float_as_uint(As[buf][mr    ][k0 + lc    ]);
                unsigned a1 = __float_as_uint(As[buf][mr + 8][k0 + lc    ]);
                unsigned a2 = __float_as_uint(As[buf][mr    ][k0 + lc + 4]);
                unsigned a3 = __float_as_uint(As[buf][mr + 8][k0 + lc + 4]);
                #pragma unroll
                for (int nt = 0; nt < 4; nt++)
                    mma_tf32(acc[mt][nt], a0, a1, a2, a3, bfr[nt][0], bfr[nt][1]);
            }
        }
        __syncthreads();
    }

    // epilogue
    #pragma unroll
    for (int mt = 0; mt < 4; mt++) {
        #pragma unroll
        for (int nt = 0; nt < 4; nt++) {
            const int row0 = bm + wm + mt * 16 + lr;
            const int col  = bn + wn + nt * 8 + lc * 2;
            float v[4];
            #pragma unroll
            for (int i = 0; i < 4; i++) {
                float t = acc[mt][nt][i];
                if (PHI) t = (t > 0.f) ? (t + 1.f) : __expf(t);   // elu(x)+1
                v[i] = t;
            }
            *(float2*)(C + (size_t)row0 * N + col)       = make_float2(v[0], v[1]);
            *(float2*)(C + (size_t)(row0 + 8) * N + col) = make_float2(v[2], v[3]);
        }
    }
}

// ---------------- Kv / K1 split-K partial reduction -------------------------
__global__ __launch_bounds__(256, 4)
void kv_reduce_kernel()
{
    const int chunk = blockIdx.x;
    const int h     = blockIdx.y;
    const int b     = blockIdx.z;
    const int bh    = b * NHEADS + h;
    const int tid   = threadIdx.x;

    __shared__ float sK[64][65];
    __shared__ float sV[64][65];

    const int tm = (tid >> 4) * 4;
    const int tn = (tid & 15) * 4;

    float acc[4][4];
    #pragma unroll
    for (int i = 0; i < 4; i++)
        #pragma unroll
        for (int j = 0; j < 4; j++) acc[i][j] = 0.f;
    float k1acc = 0.f;

    for (int sub = 0; sub < 16; sub++) {
        const int l0 = chunk * (LSEQ / NCHUNK) + sub * 64;
        for (int i = tid; i < 64 * 16; i += 256) {
            int r  = i >> 4;
            int c4 = (i & 15) << 2;
            size_t base = ((size_t)b * LSEQ + l0 + r) * DMODEL + h * DHEAD + c4;
            float4 kv = *(const float4*)(g_Kf + base);
            sK[r][c4+0]=kv.x; sK[r][c4+1]=kv.y; sK[r][c4+2]=kv.z; sK[r][c4+3]=kv.w;
            float4 vv = *(const float4*)(g_V + base);
            sV[r][c4+0]=vv.x; sV[r][c4+1]=vv.y; sV[r][c4+2]=vv.z; sV[r][c4+3]=vv.w;
        }
        __syncthreads();

        #pragma unroll 4
        for (int l = 0; l < 64; l++) {
            float a0 = sK[l][tm+0], a1 = sK[l][tm+1], a2 = sK[l][tm+2], a3 = sK[l][tm+3];
            float b0 = sV[l][tn+0], b1 = sV[l][tn+1], b2 = sV[l][tn+2], b3 = sV[l][tn+3];
            acc[0][0]+=a0*b0; acc[0][1]+=a0*b1; acc[0][2]+=a0*b2; acc[0][3]+=a0*b3;
            acc[1][0]+=a1*b0; acc[1][1]+=a1*b1; acc[1][2]+=a1*b2; acc[1][3]+=a1*b3;
            acc[2][0]+=a2*b0; acc[2][1]+=a2*b1; acc[2][2]+=a2*b2; acc[2][3]+=a2*b3;
            acc[3][0]+=a3*b0; acc[3][1]+=a3*b1; acc[3][2]+=a3*b2; acc[3][3]+=a3*b3;
        }
        if (tid < 64) {
            #pragma unroll 4
            for (int l = 0; l < 64; l++) k1acc += sK[l][tid];
        }
        __syncthreads();
    }

    #pragma unroll
    for (int i = 0; i < 4; i++)
        #pragma unroll
        for (int j = 0; j < 4; j++)
            g_KvP[(((size_t)chunk * (BATCH*NHEADS) + bh) * DHEAD + tm + i) * DHEAD + tn + j] = acc[i][j];
    if (tid < 64)
        g_K1P[((size_t)chunk * (BATCH*NHEADS) + bh) * DHEAD + tid] = k1acc;
}

// ---------------- reduce partials across chunks ------------------------------
__global__ void kv_finalize_kernel()
{
    const int i = blockIdx.x * blockDim.x + threadIdx.x;
    const int KV_ELEMS = BATCH * NHEADS * DHEAD * DHEAD;
    const int K1_ELEMS = BATCH * NHEADS * DHEAD;
    if (i < KV_ELEMS) {
        float s = 0.f;
        #pragma unroll
        for (int c = 0; c < NCHUNK; c++) s += g_KvP[(size_t)c * KV_ELEMS + i];
        g_Kv[i] = s;
    }
    if (i < K1_ELEMS) {
        float s = 0.f;
        #pragma unroll
        for (int c = 0; c < NCHUNK; c++) s += g_K1P[(size_t)c * K1_ELEMS + i];
        g_K1[i] = s;
    }
}

// ---------------- apply: attn = (Qf @ Kv) / (Qf @ K1 + eps) ------------------
__global__ __launch_bounds__(256, 4)
void attn_apply_kernel()
{
    const int lt = blockIdx.x;
    const int h  = blockIdx.y;
    const int b  = blockIdx.z;
    const int bh = b * NHEADS + h;
    const int tid = threadIdx.x;

    __shared__ float sQ [64][65];
    __shared__ float sKv[64][65];
    __shared__ float sK1[64];
    __shared__ float sden[64];

    for (int i = tid; i < 64 * 16; i += 256) {
        int r  = i >> 4;
        int c4 = (i & 15) << 2;
        size_t qbase = ((size_t)b * LSEQ + lt * 64 + r) * DMODEL + h * DHEAD + c4;
        float4 qv = *(const float4*)(g_Qf + qbase);
        sQ[r][c4+0]=qv.x; sQ[r][c4+1]=qv.y; sQ[r][c4+2]=qv.z; sQ[r][c4+3]=qv.w;
        float4 kv = *(const float4*)(g_Kv + ((size_t)bh * DHEAD + r) * DHEAD + c4);
        sKv[r][c4+0]=kv.x; sKv[r][c4+1]=kv.y; sKv[r][c4+2]=kv.z; sKv[r][c4+3]=kv.w;
    }
    if (tid < 64) sK1[tid] = g_K1[(size_t)bh * DHEAD + tid];
    __syncthreads();

    if (tid < 64) {
        float d = 0.f;
        #pragma unroll
        for (int m = 0; m < 64; m++) d += sQ[tid][m] * sK1[m];
        sden[tid] = d + EPSV;
    }
    __syncthreads();

    const int tm = (tid >> 4) * 4;
    const int tn = (tid & 15) * 4;
    float acc[4][4];
    #pragma unroll
    for (int i = 0; i < 4; i++)
        #pragma unroll
        for (int j = 0; j < 4; j++) acc[i][j] = 0.f;

    #pragma unroll 4
    for (int m = 0; m < 64; m++) {
        float a0 = sQ[tm+0][m], a1 = sQ[tm+1][m], a2 = sQ[tm+2][m], a3 = sQ[tm+3][m];
        float b0 = sKv[m][tn+0], b1 = sKv[m][tn+1], b2 = sKv[m][tn+2], b3 = sKv[m][tn+3];
        acc[0][0]+=a0*b0; acc[0][1]+=a0*b1; acc[0][2]+=a0*b2; acc[0][3]+=a0*b3;
        acc[1][0]+=a1*b0; acc[1][1]+=a1*b1; acc[1][2]+=a1*b2; acc[1][3]+=a1*b3;
        acc[2][0]+=a2*b0; acc[2][1]+=a2*b1; acc[2][2]+=a2*b2; acc[2][3]+=a2*b3;
        acc[3][0]+=a3*b0; acc[3][1]+=a3*b1; acc[3][2]+=a3*b2; acc[3][3]+=a3*b3;
    }

    #pragma unroll
    for (int i = 0; i < 4; i++) {
        float inv = 1.f / sden[tm + i];
        size_t base = ((size_t)b * LSEQ + lt * 64 + tm + i) * DMODEL + h * DHEAD + tn;
        *(float4*)(g_attn + base) =
            make_float4(acc[i][0]*inv, acc[i][1]*inv, acc[i][2]*inv, acc[i][3]*inv);
    }
}

// ---------------- launch ------------------------------------------------------
extern "C" void kernel_launch(void* const* d_in, const int* in_sizes, int n_in,
                              void* d_out, int out_size)
{
    const float* x  = (const float*)d_in[0];
    const float* Wq = (const float*)d_in[1];
    const float* Wk = (const float*)d_in[2];
    const float* Wv = (const float*)d_in[3];
    const float* Wo = (const float*)d_in[4];
    float* out = (float*)d_out;

    float *pQf, *pKf, *pV, *pAttn;
    cudaGetSymbolAddress((void**)&pQf,   g_Qf);
    cudaGetSymbolAddress((void**)&pKf,   g_Kf);
    cudaGetSymbolAddress((void**)&pV,    g_V);
    cudaGetSymbolAddress((void**)&pAttn, g_attn);

    dim3 gemm_grid(DMODEL / 128, MROWS / 128);   // (8, 256)

    gemm_tf32_kernel<1><<<gemm_grid, 256>>>(x, Wq, pQf, MROWS, DMODEL, DMODEL);
    gemm_tf32_kernel<1><<<gemm_grid, 256>>>(x, Wk, pKf, MROWS, DMODEL, DMODEL);
    gemm_tf32_kernel<0><<<gemm_grid, 256>>>(x, Wv, pV,  MROWS, DMODEL, DMODEL);

    kv_reduce_kernel<<<dim3(NCHUNK, NHEADS, BATCH), 256>>>();
    kv_finalize_kernel<<<(BATCH*NHEADS*DHEAD*DHEAD + 255) / 256, 256>>>();

    attn_apply_kernel<<<dim3(LSEQ / 64, NHEADS, BATCH), 256>>>();

    gemm_tf32_kernel<0><<<gemm_grid, 256>>>(pAttn, Wo, out, MROWS, DMODEL, DMODEL);
}

// round 5
// speedup vs baseline: 3.1230x; 1.1543x over previous
#include <cuda_runtime.h>
#include <math.h>

#define BATCH   4
#define LSEQ    8192
#define DMODEL  1024
#define NHEADS  16
#define DHEAD   64
#define MROWS   (BATCH * LSEQ)          // 32768
#define NCHUNK  32
#define EPSV    1e-6f

#define GSTAGES 4                       // cp.async pipeline depth

// ---------------- scratch (device globals; no allocations allowed) ----------
static __device__ float g_xr  [(size_t)MROWS * DMODEL];                 // tf32-rounded x
static __device__ float g_Wr  [(size_t)4 * DMODEL * DMODEL];            // rounded Wq,Wk,Wv,Wo
static __device__ float g_Qf  [(size_t)MROWS * DMODEL];
static __device__ float g_Kf  [(size_t)MROWS * DMODEL];
static __device__ float g_V   [(size_t)MROWS * DMODEL];
static __device__ float g_attn[(size_t)MROWS * DMODEL];                 // tf32-rounded at write
static __device__ float g_KvP [(size_t)NCHUNK * BATCH * NHEADS * DHEAD * DHEAD];
static __device__ float g_K1P [(size_t)NCHUNK * BATCH * NHEADS * DHEAD];
static __device__ float g_Kv  [(size_t)BATCH * NHEADS * DHEAD * DHEAD];
static __device__ float g_K1  [(size_t)BATCH * NHEADS * DHEAD];

// ---------------- helpers ----------------------------------------------------
__device__ __forceinline__ float f2tf32(float x) {
    unsigned r;
    asm("cvt.rna.tf32.f32 %0, %1;" : "=r"(r) : "f"(x));
    return __uint_as_float(r);
}

__device__ __forceinline__ void mma_tf32(float c[4],
                                         unsigned a0, unsigned a1, unsigned a2, unsigned a3,
                                         unsigned b0, unsigned b1)
{
    asm volatile("mma.sync.aligned.m16n8k8.row.col.f32.tf32.tf32.f32 "
                 "{%0,%1,%2,%3}, {%4,%5,%6,%7}, {%8,%9}, {%0,%1,%2,%3};"
                 : "+f"(c[0]), "+f"(c[1]), "+f"(c[2]), "+f"(c[3])
                 : "r"(a0), "r"(a1), "r"(a2), "r"(a3), "r"(b0), "r"(b1));
}

__device__ __forceinline__ void cp_async16(void* sptr, const void* gptr) {
    unsigned sa = (unsigned)__cvta_generic_to_shared(sptr);
    asm volatile("cp.async.cg.shared.global [%0], [%1], 16;" :: "r"(sa), "l"(gptr));
}
__device__ __forceinline__ void cp_commit() {
    asm volatile("cp.async.commit_group;");
}
template <int N>
__device__ __forceinline__ void cp_wait() {
    asm volatile("cp.async.wait_group %0;" :: "n"(N));
}

// ---------------- tf32-rounding pre-pass -------------------------------------
__global__ void round_tf32_kernel(const float* __restrict__ in, float* __restrict__ out, int n4)
{
    int i = blockIdx.x * blockDim.x + threadIdx.x;
    if (i < n4) {
        float4 v = ((const float4*)in)[i];
        ((float4*)out)[i] = make_float4(f2tf32(v.x), f2tf32(v.y), f2tf32(v.z), f2tf32(v.w));
    }
}

// ---------------- TF32 tensor-core GEMM, cp.async multistage ------------------
// C[M,N] = A[M,K] @ B[K,N], inputs already tf32-rounded.
// 128x128 block tile, BK=16, 256 threads (8 warps 2x4), warp 64x32 (4x4 mmas).
// Dynamic smem: GSTAGES * (As 128x20 + Bs 16x136) floats.
#define AS(s,r,c) Asm[((s)*128 + (r))*20 + (c)]
#define BS(s,r,c) Bsm[((s)*16  + (r))*136 + (c)]
#define GEMM_SMEM_FLOATS (GSTAGES * (128*20 + 16*136))

template <int PHI>
__global__ __launch_bounds__(256, 2)
void gemm_tf32_kernel(const float* __restrict__ A, const float* __restrict__ B,
                      float* __restrict__ C, int M, int N, int K)
{
    extern __shared__ float sm[];
    float* Asm = sm;
    float* Bsm = sm + GSTAGES * 128 * 20;

    const int tid  = threadIdx.x;
    const int bm   = blockIdx.y * 128;
    const int bn   = blockIdx.x * 128;
    const int lane = tid & 31;
    const int warp = tid >> 5;
    const int wm   = (warp >> 2) * 64;
    const int wn   = (warp & 3) * 32;
    const int lr   = lane >> 2;
    const int lc   = lane & 3;

    const int ar0 = tid >> 2;             // 0..63
    const int ac0 = (tid & 3) * 4;
    const int ar1 = ar0 + 64;             // 64..127
    const int br0 = tid >> 5;             // 0..7
    const int bc0 = (tid & 31) * 4;
    const int br1 = br0 + 8;              // 8..15

    float acc[4][4][4];
    #pragma unroll
    for (int mt = 0; mt < 4; mt++)
        #pragma unroll
        for (int nt = 0; nt < 4; nt++)
            #pragma unroll
            for (int i = 0; i < 4; i++) acc[mt][nt][i] = 0.f;

    const int KT = K >> 4;

    // prologue: fill GSTAGES-1 stages
    #pragma unroll
    for (int s = 0; s < GSTAGES - 1; s++) {
        const int ko = s << 4;
        cp_async16(&AS(s, ar0, ac0), A + (size_t)(bm + ar0) * K + ko + ac0);
        cp_async16(&AS(s, ar1, ac0), A + (size_t)(bm + ar1) * K + ko + ac0);
        cp_async16(&BS(s, br0, bc0), B + (size_t)(ko + br0) * N + bn + bc0);
        cp_async16(&BS(s, br1, bc0), B + (size_t)(ko + br1) * N + bn + bc0);
        cp_commit();
    }
    cp_wait<GSTAGES - 2>();
    __syncthreads();

    #pragma unroll 1
    for (int kt = 0; kt < KT; kt++) {
        const int buf = kt & (GSTAGES - 1);

        // issue loads for kt + GSTAGES-1 (always commit to keep group math uniform)
        {
            const int ktn = kt + GSTAGES - 1;
            if (ktn < KT) {
                const int s  = ktn & (GSTAGES - 1);
                const int ko = ktn << 4;
                cp_async16(&AS(s, ar0, ac0), A + (size_t)(bm + ar0) * K + ko + ac0);
                cp_async16(&AS(s, ar1, ac0), A + (size_t)(bm + ar1) * K + ko + ac0);
                cp_async16(&BS(s, br0, bc0), B + (size_t)(ko + br0) * N + bn + bc0);
                cp_async16(&BS(s, br1, bc0), B + (size_t)(ko + br1) * N + bn + bc0);
            }
            cp_commit();
        }

        // compute current buffer
        #pragma unroll
        for (int ks = 0; ks < 2; ks++) {
            const int k0 = ks * 8;
            unsigned bfr[4][2];
            #pragma unroll
            for (int nt = 0; nt < 4; nt++) {
                bfr[nt][0] = __float_as_uint(BS(buf, k0 + lc,     wn + nt * 8 + lr));
                bfr[nt][1] = __float_as_uint(BS(buf, k0 + lc + 4, wn + nt * 8 + lr));
            }
            #pragma unroll
            for (int mt = 0; mt < 4; mt++) {
                const int mr = wm + mt * 16 + lr;
                unsigned a0 = __float_as_uint(AS(buf, mr,     k0 + lc));
                unsigned a1 = __float_as_uint(AS(buf, mr + 8, k0 + lc));
                unsigned a2 = __float_as_uint(AS(buf, mr,     k0 + lc + 4));
                unsigned a3 = __float_as_uint(AS(buf, mr + 8, k0 + lc + 4));
                #pragma unroll
                for (int nt = 0; nt < 4; nt++)
                    mma_tf32(acc[mt][nt], a0, a1, a2, a3, bfr[nt][0], bfr[nt][1]);
            }
        }

        cp_wait<GSTAGES - 2>();
        __syncthreads();
    }

    // epilogue
    #pragma unroll
    for (int mt = 0; mt < 4; mt++) {
        #pragma unroll
        for (int nt = 0; nt < 4; nt++) {
            const int row0 = bm + wm + mt * 16 + lr;
            const int col  = bn + wn + nt * 8 + lc * 2;
            float v[4];
            #pragma unroll
            for (int i = 0; i < 4; i++) {
                float t = acc[mt][nt][i];
                if (PHI) t = (t > 0.f) ? (t + 1.f) : __expf(t);   // elu(x)+1
                v[i] = t;
            }
            *(float2*)(C + (size_t)row0 * N + col)       = make_float2(v[0], v[1]);
            *(float2*)(C + (size_t)(row0 + 8) * N + col) = make_float2(v[2], v[3]);
        }
    }
}

// ---------------- Kv / K1 split-K partial reduction -------------------------
// grid (NCHUNK, H, B): each block reduces L/NCHUNK = 256 rows (4 sub-tiles of 64).
__global__ __launch_bounds__(256, 4)
void kv_reduce_kernel()
{
    const int chunk = blockIdx.x;
    const int h     = blockIdx.y;
    const int b     = blockIdx.z;
    const int bh    = b * NHEADS + h;
    const int tid   = threadIdx.x;

    __shared__ float sK[64][65];
    __shared__ float sV[64][65];

    const int tm = (tid >> 4) * 4;
    const int tn = (tid & 15) * 4;

    float acc[4][4];
    #pragma unroll
    for (int i = 0; i < 4; i++)
        #pragma unroll
        for (int j = 0; j < 4; j++) acc[i][j] = 0.f;
    float k1acc = 0.f;

    const int SUBS = (LSEQ / NCHUNK) / 64;   // 4
    for (int sub = 0; sub < SUBS; sub++) {
        const int l0 = chunk * (LSEQ / NCHUNK) + sub * 64;
        for (int i = tid; i < 64 * 16; i += 256) {
            int r  = i >> 4;
            int c4 = (i & 15) << 2;
            size_t base = ((size_t)b * LSEQ + l0 + r) * DMODEL + h * DHEAD + c4;
            float4 kv = *(const float4*)(g_Kf + base);
            sK[r][c4+0]=kv.x; sK[r][c4+1]=kv.y; sK[r][c4+2]=kv.z; sK[r][c4+3]=kv.w;
            float4 vv = *(const float4*)(g_V + base);
            sV[r][c4+0]=vv.x; sV[r][c4+1]=vv.y; sV[r][c4+2]=vv.z; sV[r][c4+3]=vv.w;
        }
        __syncthreads();

        #pragma unroll 4
        for (int l = 0; l < 64; l++) {
            float a0 = sK[l][tm+0], a1 = sK[l][tm+1], a2 = sK[l][tm+2], a3 = sK[l][tm+3];
            float b0 = sV[l][tn+0], b1 = sV[l][tn+1], b2 = sV[l][tn+2], b3 = sV[l][tn+3];
            acc[0][0]+=a0*b0; acc[0][1]+=a0*b1; acc[0][2]+=a0*b2; acc[0][3]+=a0*b3;
            acc[1][0]+=a1*b0; acc[1][1]+=a1*b1; acc[1][2]+=a1*b2; acc[1][3]+=a1*b3;
            acc[2][0]+=a2*b0; acc[2][1]+=a2*b1; acc[2][2]+=a2*b2; acc[2][3]+=a2*b3;
            acc[3][0]+=a3*b0; acc[3][1]+=a3*b1; acc[3][2]+=a3*b2; acc[3][3]+=a3*b3;
        }
        if (tid < 64) {
            #pragma unroll 4
            for (int l = 0; l < 64; l++) k1acc += sK[l][tid];
        }
        __syncthreads();
    }

    #pragma unroll
    for (int i = 0; i < 4; i++)
        #pragma unroll
        for (int j = 0; j < 4; j++)
            g_KvP[(((size_t)chunk * (BATCH*NHEADS) + bh) * DHEAD + tm + i) * DHEAD + tn + j] = acc[i][j];
    if (tid < 64)
        g_K1P[((size_t)chunk * (BATCH*NHEADS) + bh) * DHEAD + tid] = k1acc;
}

// ---------------- reduce partials across chunks ------------------------------
__global__ void kv_finalize_kernel()
{
    const int i = blockIdx.x * blockDim.x + threadIdx.x;
    const int KV_ELEMS = BATCH * NHEADS * DHEAD * DHEAD;
    const int K1_ELEMS = BATCH * NHEADS * DHEAD;
    if (i < KV_ELEMS) {
        float s = 0.f;
        #pragma unroll
        for (int c = 0; c < NCHUNK; c++) s += g_KvP[(size_t)c * KV_ELEMS + i];
        g_Kv[i] = s;
    }
    if (i < K1_ELEMS) {
        float s = 0.f;
        #pragma unroll
        for (int c = 0; c < NCHUNK; c++) s += g_K1P[(size_t)c * K1_ELEMS + i];
        g_K1[i] = s;
    }
}

// ---------------- apply: attn = (Qf @ Kv) / (Qf @ K1 + eps) ------------------
// Output stored tf32-rounded (it feeds only the Wo GEMM).
__global__ __launch_bounds__(256, 4)
void attn_apply_kernel()
{
    const int lt = blockIdx.x;
    const int h  = blockIdx.y;
    const int b  = blockIdx.z;
    const int bh = b * NHEADS + h;
    const int tid = threadIdx.x;

    __shared__ float sQ [64][65];
    __shared__ float sKv[64][65];
    __shared__ float sK1[64];
    __shared__ float sden[64];

    for (int i = tid; i < 64 * 16; i += 256) {
        int r  = i >> 4;
        int c4 = (i & 15) << 2;
        size_t qbase = ((size_t)b * LSEQ + lt * 64 + r) * DMODEL + h * DHEAD + c4;
        float4 qv = *(const float4*)(g_Qf + qbase);
        sQ[r][c4+0]=qv.x; sQ[r][c4+1]=qv.y; sQ[r][c4+2]=qv.z; sQ[r][c4+3]=qv.w;
        float4 kv = *(const float4*)(g_Kv + ((size_t)bh * DHEAD + r) * DHEAD + c4);
        sKv[r][c4+0]=kv.x; sKv[r][c4+1]=kv.y; sKv[r][c4+2]=kv.z; sKv[r][c4+3]=kv.w;
    }
    if (tid < 64) sK1[tid] = g_K1[(size_t)bh * DHEAD + tid];
    __syncthreads();

    if (tid < 64) {
        float d = 0.f;
        #pragma unroll
        for (int m = 0; m < 64; m++) d += sQ[tid][m] * sK1[m];
        sden[tid] = d + EPSV;
    }
    __syncthreads();

    const int tm = (tid >> 4) * 4;
    const int tn = (tid & 15) * 4;
    float acc[4][4];
    #pragma unroll
    for (int i = 0; i < 4; i++)
        #pragma unroll
        for (int j = 0; j < 4; j++) acc[i][j] = 0.f;

    #pragma unroll 4
    for (int m = 0; m < 64; m++) {
        float a0 = sQ[tm+0][m], a1 = sQ[tm+1][m], a2 = sQ[tm+2][m], a3 = sQ[tm+3][m];
        float b0 = sKv[m][tn+0], b1 = sKv[m][tn+1], b2 = sKv[m][tn+2], b3 = sKv[m][tn+3];
        acc[0][0]+=a0*b0; acc[0][1]+=a0*b1; acc[0][2]+=a0*b2; acc[0][3]+=a0*b3;
        acc[1][0]+=a1*b0; acc[1][1]+=a1*b1; acc[1][2]+=a1*b2; acc[1][3]+=a1*b3;
        acc[2][0]+=a2*b0; acc[2][1]+=a2*b1; acc[2][2]+=a2*b2; acc[2][3]+=a2*b3;
        acc[3][0]+=a3*b0; acc[3][1]+=a3*b1; acc[3][2]+=a3*b2; acc[3][3]+=a3*b3;
    }

    #pragma unroll
    for (int i = 0; i < 4; i++) {
        float inv = 1.f / sden[tm + i];
        size_t base = ((size_t)b * LSEQ + lt * 64 + tm + i) * DMODEL + h * DHEAD + tn;
        *(float4*)(g_attn + base) = make_float4(f2tf32(acc[i][0]*inv), f2tf32(acc[i][1]*inv),
                                                f2tf32(acc[i][2]*inv), f2tf32(acc[i][3]*inv));
    }
}

// ---------------- launch ------------------------------------------------------
extern "C" void kernel_launch(void* const* d_in, const int* in_sizes, int n_in,
                              void* d_out, int out_size)
{
    const float* x  = (const float*)d_in[0];
    const float* Wq = (const float*)d_in[1];
    const float* Wk = (const float*)d_in[2];
    const float* Wv = (const float*)d_in[3];
    const float* Wo = (const float*)d_in[4];
    float* out = (float*)d_out;

    float *pXr, *pWr, *pQf, *pKf, *pV, *pAttn;
    cudaGetSymbolAddress((void**)&pXr,   g_xr);
    cudaGetSymbolAddress((void**)&pWr,   g_Wr);
    cudaGetSymbolAddress((void**)&pQf,   g_Qf);
    cudaGetSymbolAddress((void**)&pKf,   g_Kf);
    cudaGetSymbolAddress((void**)&pV,    g_V);
    cudaGetSymbolAddress((void**)&pAttn, g_attn);

    const int gemm_smem = GEMM_SMEM_FLOATS * (int)sizeof(float);   // ~75.8 KB
    cudaFuncSetAttribute(gemm_tf32_kernel<0>, cudaFuncAttributeMaxDynamicSharedMemorySize, gemm_smem);
    cudaFuncSetAttribute(gemm_tf32_kernel<1>, cudaFuncAttributeMaxDynamicSharedMemorySize, gemm_smem);

    // pre-round operands to tf32
    const int WN = DMODEL * DMODEL;                  // 1M
    round_tf32_kernel<<<(MROWS * DMODEL / 4 + 255) / 256, 256>>>(x, pXr, MROWS * DMODEL / 4);
    round_tf32_kernel<<<(WN / 4 + 255) / 256, 256>>>(Wq, pWr + 0 * (size_t)WN, WN / 4);
    round_tf32_kernel<<<(WN / 4 + 255) / 256, 256>>>(Wk, pWr + 1 * (size_t)WN, WN / 4);
    round_tf32_kernel<<<(WN / 4 + 255) / 256, 256>>>(Wv, pWr + 2 * (size_t)WN, WN / 4);
    round_tf32_kernel<<<(WN / 4 + 255) / 256, 256>>>(Wo, pWr + 3 * (size_t)WN, WN / 4);

    dim3 gemm_grid(DMODEL / 128, MROWS / 128);       // (8, 256)

    gemm_tf32_kernel<1><<<gemm_grid, 256, gemm_smem>>>(pXr, pWr + 0 * (size_t)WN, pQf, MROWS, DMODEL, DMODEL);
    gemm_tf32_kernel<1><<<gemm_grid, 256, gemm_smem>>>(pXr, pWr + 1 * (size_t)WN, pKf, MROWS, DMODEL, DMODEL);
    gemm_tf32_kernel<0><<<gemm_grid, 256, gemm_smem>>>(pXr, pWr + 2 * (size_t)WN, pV,  MROWS, DMODEL, DMODEL);

    kv_reduce_kernel<<<dim3(NCHUNK, NHEADS, BATCH), 256>>>();
    kv_finalize_kernel<<<(BATCH*NHEADS*DHEAD*DHEAD + 255) / 256, 256>>>();

    attn_apply_kernel<<<dim3(LSEQ / 64, NHEADS, BATCH), 256>>>();

    gemm_tf32_kernel<0><<<gemm_grid, 256, gemm_smem>>>(pAttn, pWr + 3 * (size_t)WN, out, MROWS, DMODEL, DMODEL);
}